// round 9
// baseline (speedup 1.0000x reference)
#include <cuda_runtime.h>

#define Nn 8
#define Cc 64
#define Hh 256
#define Ww 256
#define Pp 16          // cluster: 8 col-groups x 2 ch-groups
#define WC 32
#define FSTR 34
#define NT 256         // 8 warps: warp = 4 out-ch x 32 cols
#define HW (Hh*Ww)

// float-index smem offsets
#define WS_F 0
#define FBA_F(b) (6144 + (b)*2176)     // batch A fn tiles [64][34] x2
#define FBB_F(b) (10496 + (b)*2176)    // batch B fn tiles
#define MLA_F 14848                    // batch A mail [16][64]
#define MLB_F 15872                    // batch B mail
#define MRA_F 16896                    // batch A mean|rstd (64)
#define MRB_F 16960                    // batch B mean|rstd
#define SMEM_BYTES (17024*4)

__device__ float g_stack[(size_t)Nn * Cc * Hh * Ww];

extern __shared__ float sm[];

__device__ __forceinline__ void carr() {
    asm volatile("barrier.cluster.arrive.aligned;" ::: "memory");
}
__device__ __forceinline__ void cwait() {
    asm volatile("barrier.cluster.wait.aligned;" ::: "memory");
}
__device__ __forceinline__ void csync() { carr(); cwait(); }
__device__ __forceinline__ unsigned mapa_rank(unsigned laddr, unsigned rank) {
    unsigned ra;
    asm("mapa.shared::cluster.u32 %0, %1, %2;" : "=r"(ra) : "r"(laddr), "r"(rank));
    return ra;
}
__device__ __forceinline__ void st_cl_f32(unsigned a, float v) {
    asm volatile("st.shared::cluster.f32 [%0], %1;" :: "r"(a), "f"(v) : "memory");
}
__device__ __forceinline__ void st_cl_b64(unsigned a, unsigned long long v) {
    asm volatile("st.shared::cluster.b64 [%0], %1;" :: "r"(a), "l"(v) : "memory");
}

// ---- packed f32x2 helpers ----
__device__ __forceinline__ unsigned long long splat2(float a) {
    unsigned long long r; unsigned u = __float_as_uint(a);
    asm("mov.b64 %0, {%1, %1};" : "=l"(r) : "r"(u));
    return r;
}
__device__ __forceinline__ void fma2(unsigned long long& d, unsigned long long a, unsigned long long b) {
    asm("fma.rn.f32x2 %0, %1, %2, %0;" : "+l"(d) : "l"(a), "l"(b));
}
__device__ __forceinline__ unsigned long long add2(unsigned long long a, unsigned long long b) {
    unsigned long long d;
    asm("add.rn.f32x2 %0, %1, %2;" : "=l"(d) : "l"(a), "l"(b));
    return d;
}
__device__ __forceinline__ unsigned long long mul2(unsigned long long a, unsigned long long b) {
    unsigned long long d;
    asm("mul.rn.f32x2 %0, %1, %2;" : "=l"(d) : "l"(a), "l"(b));
    return d;
}
__device__ __forceinline__ void unpack2(unsigned long long v, float& lo, float& hi) {
    unsigned ul, uh;
    asm("mov.b64 {%0, %1}, %2;" : "=r"(ul), "=r"(uh) : "l"(v));
    lo = __uint_as_float(ul); hi = __uint_as_float(uh);
}

// conv over 64 in-ch: warp = 4 out-ch (ob..ob+3) x 32 cols (lane)
__device__ __forceinline__ void conv_row(const float* __restrict__ fbR,
                                         const float* __restrict__ Ws,
                                         int lane, int ob,
                                         unsigned long long& acc0,
                                         unsigned long long& acc1)
{
    acc0 = 0ull; acc1 = 0ull;
#pragma unroll 8
    for (int i = 0; i < Cc; i++) {
        float a0 = fbR[i * FSTR + lane];
        float a1 = fbR[i * FSTR + lane + 1];
        float a2 = fbR[i * FSTR + lane + 2];
        unsigned long long s0 = splat2(a0), s1 = splat2(a1), s2 = splat2(a2);
        const float* wp = Ws + i * 96 + ob;
        ulonglong2 t0 = *(const ulonglong2*)(wp);
        ulonglong2 t1 = *(const ulonglong2*)(wp + 32);
        ulonglong2 t2 = *(const ulonglong2*)(wp + 64);
        fma2(acc0, s0, t0.x); fma2(acc1, s0, t0.y);
        fma2(acc0, s1, t1.x); fma2(acc1, s1, t1.y);
        fma2(acc0, s2, t2.x); fma2(acc1, s2, t2.y);
    }
}

// butterfly reduce + push partials to the 8 same-cg ranks' mailboxes
__device__ __forceinline__ void reduce_mail(float* smp,
    unsigned long long acc0, unsigned long long acc1,
    int lane, int ob, unsigned rank, unsigned mlB,
    const unsigned* __restrict__ pbSame, unsigned smu)
{
    unsigned long long s0r = acc0, s1r = acc1;
    unsigned long long q0r = mul2(acc0, acc0), q1r = mul2(acc1, acc1);
#pragma unroll
    for (int off = 16; off >= 1; off >>= 1) {
        s0r = add2(s0r, __shfl_xor_sync(0xffffffffu, s0r, off));
        s1r = add2(s1r, __shfl_xor_sync(0xffffffffu, s1r, off));
        q0r = add2(q0r, __shfl_xor_sync(0xffffffffu, q0r, off));
        q1r = add2(q1r, __shfl_xor_sync(0xffffffffu, q1r, off));
    }
    if (lane < 4) {
        int j   = lane & 1;
        int isq = lane >> 1;
        unsigned long long val = isq ? (j ? q1r : q0r) : (j ? s1r : s0r);
        unsigned moff = mlB + (unsigned)((int)rank * 64 + isq * 32 + ob + 2 * j) * 4u;
        *(unsigned long long*)((char*)smp + moff) = val;   // local slot
#pragma unroll
        for (int p = 0; p < 8; p++) {
            unsigned pb = pbSame[p];
            if (pb != smu) st_cl_b64(pb + moff, val);
        }
    }
}

__device__ __forceinline__ void stats32(const float* __restrict__ ml, int cg,
                                        int tid, float* __restrict__ mr)
{
    if (tid < 32) {
        float sv = 0.f, qv = 0.f;
#pragma unroll
        for (int g2 = 0; g2 < 8; g2++) {
            int r2 = 2 * g2 + cg;
            sv += ml[r2 * 64 + tid];
            qv += ml[r2 * 64 + 32 + tid];
        }
        float mean = sv * (1.f / 256.f);
        float var  = qv * (1.f / 256.f) - mean * mean;
        mr[tid]      = mean;
        mr[32 + tid] = rsqrtf(var + 1e-5f);
    }
}

// normalize + ELU + residual; write local fbW + remote pushes; fn out in regs
__device__ __forceinline__ void epilogue(unsigned long long acc0, unsigned long long acc1,
    const float* __restrict__ mr, const float* __restrict__ xr,
    float* __restrict__ fbW, unsigned fbWB,
    int lane, int ob, int cbase, int hasL, int hasR,
    unsigned pbP, unsigned pbL0, unsigned pbL1, unsigned pbR0, unsigned pbR1,
    float* __restrict__ fn)
{
    float av[4];
    unpack2(acc0, av[0], av[1]);
    unpack2(acc1, av[2], av[3]);
#pragma unroll
    for (int k = 0; k < 4; k++) {
        int chl = ob + k;
        float m = mr[chl], r = mr[32 + chl];
        float v = (av[k] - m) * r;
        v = v > 0.f ? v : (__expf(v) - 1.f);
        float f = v + xr[k];
        fn[k] = f;
        int chg = cbase + chl;
        fbW[chg * FSTR + 1 + lane] = f;
        unsigned off = fbWB + (unsigned)(chg * FSTR + 1 + lane) * 4u;
        st_cl_f32(pbP + off, f);
        if (lane == 0 && hasL) {
            unsigned ho = fbWB + (unsigned)(chg * FSTR + 33) * 4u;
            st_cl_f32(pbL0 + ho, f); st_cl_f32(pbL1 + ho, f);
        }
        if (lane == 31 && hasR) {
            unsigned ho = fbWB + (unsigned)(chg * FSTR + 0) * 4u;
            st_cl_f32(pbR0 + ho, f); st_cl_f32(pbR1 + ho, f);
        }
    }
}

__device__ __forceinline__ void writeback(const float* __restrict__ fn,
    float* __restrict__ dst, int row, int cbase, int ob, int w0, int lane)
{
#pragma unroll
    for (int k = 0; k < 4; k++)
        dst[(size_t)(cbase + ob + k) * HW + (size_t)row * Ww + w0 + lane] = fn[k];
}

__device__ __forceinline__ void prefetch_xr(const float* __restrict__ src,
    int row, int cbase, int ob, int w0, int lane, float* __restrict__ xr)
{
#pragma unroll
    for (int k = 0; k < 4; k++)
        xr[k] = src[(size_t)(cbase + ob + k) * HW + (size_t)row * Ww + w0 + lane];
}

__global__ void __launch_bounds__(NT, 1) __cluster_dims__(Pp, 1, 1)
dirconv_kernel(const float* __restrict__ x, const float* __restrict__ Wg,
               float* __restrict__ out)
{
    float* Ws = sm;
    const unsigned smu = (unsigned)__cvta_generic_to_shared(sm);

    const int tid  = threadIdx.x;
    const int lane = tid & 31;
    const int warp = tid >> 5;
    const int ob   = warp * 4;
    unsigned rank;
    asm("mov.u32 %0, %%cluster_ctarank;" : "=r"(rank));
    const int g     = (int)(rank >> 1);
    const int cg    = (int)(rank & 1u);
    const int cbase = cg * 32;
    const int w0    = g * WC;
    const int cid   = blockIdx.x / Pp;      // 0..3
    const int bA    = 2 * cid, bB = 2 * cid + 1;
    const int hasL  = (g > 0), hasR = (g < 7);

    const float* xbA = x + (size_t)bA * Cc * HW;
    const float* xbB = x + (size_t)bB * Cc * HW;
    float* stkA = g_stack + (size_t)bA * Cc * HW;
    float* stkB = g_stack + (size_t)bB * Cc * HW;
    float* outA = out + (size_t)bA * Cc * HW;
    float* outB = out + (size_t)bB * Cc * HW;

    const unsigned pbP  = mapa_rank(smu, rank ^ 1u);
    const unsigned basr = rank & ~1u;
    const unsigned pbL0 = mapa_rank(smu, hasL ? basr - 2u : 0u);
    const unsigned pbL1 = mapa_rank(smu, hasL ? basr - 1u : 0u);
    const unsigned pbR0 = mapa_rank(smu, hasR ? basr + 2u : 0u);
    const unsigned pbR1 = mapa_rank(smu, hasR ? basr + 3u : 0u);
    unsigned pbSame[8];
#pragma unroll
    for (int gg = 0; gg < 8; gg++)
        pbSame[gg] = mapa_rank(smu, 2u * (unsigned)gg + (unsigned)cg);

    // stage weights: Ws[i*96 + tap*32 + ol] = W[cbase+ol][i][1][tap] (bias cancels in IN)
    for (int idx = tid; idx < 6144; idx += NT) {
        int i   = idx / 96;
        int rem = idx - i * 96;
        int tap = rem >> 5;
        int ol  = rem & 31;
        Ws[idx] = Wg[(size_t)(cbase + ol) * 576 + i * 9 + 3 + tap];
    }

    // f[0] = x[0] for both batches: full 64ch x 34col windows, stacks row 0
    for (int idx = tid; idx < 2176; idx += NT) {
        int ch = idx / 34;
        int c  = idx - ch * 34;
        int gcol = w0 - 1 + c;
        int valid = (gcol >= 0 && gcol < Ww);
        float vA = valid ? xbA[(size_t)ch * HW + gcol] : 0.f;
        float vB = valid ? xbB[(size_t)ch * HW + gcol] : 0.f;
        sm[FBA_F(0) + ch * FSTR + c] = vA;
        sm[FBB_F(0) + ch * FSTR + c] = vB;
        if ((ch >> 5) == cg && valid && c >= 1 && c <= 32) {
            stkA[(size_t)ch * HW + gcol] = vA;
            stkB[(size_t)ch * HW + gcol] = vB;
        }
    }
    // zero cluster-edge halos (both buffers, both batches)
    if (g == 0 && tid < 64) {
        sm[FBA_F(0) + tid * FSTR] = 0.f; sm[FBA_F(1) + tid * FSTR] = 0.f;
        sm[FBB_F(0) + tid * FSTR] = 0.f; sm[FBB_F(1) + tid * FSTR] = 0.f;
    }
    if (g == 7 && tid < 64) {
        sm[FBA_F(0) + tid * FSTR + 33] = 0.f; sm[FBA_F(1) + tid * FSTR + 33] = 0.f;
        sm[FBB_F(0) + tid * FSTR + 33] = 0.f; sm[FBB_F(1) + tid * FSTR + 33] = 0.f;
    }

    float xrA[4], xrB[4];
    prefetch_xr(xbA, 1, cbase, ob, w0, lane, xrA);
    prefetch_xr(xbB, 1, cbase, ob, w0, lane, xrB);

    csync();   // everyone staged; phases start clean

    for (int t = 1; t <= 510; ++t) {
        const int fwd  = (t <= 255);
        const int row  = fwd ? t : 510 - t;
        const int pbuf = t & 1;
        const unsigned mlAB = (unsigned)(MLA_F * 4);
        const unsigned mlBB = (unsigned)(MLB_F * 4);

        // ---- A: conv + reduce + mail push
        unsigned long long a0, a1;
        conv_row(sm + FBA_F(pbuf ^ 1), Ws, lane, ob, a0, a1);
        reduce_mail(sm, a0, a1, lane, ob, rank, mlAB, pbSame, smu);
        carr();                                    // p1: releases mailA

        // ---- B: conv + reduce + mail push (hides p1 latency)
        unsigned long long b0, b1;
        conv_row(sm + FBB_F(pbuf ^ 1), Ws, lane, ob, b0, b1);
        reduce_mail(sm, b0, b1, lane, ob, rank, mlBB, pbSame, smu);
        cwait();                                   // p1 done: mailA visible

        // ---- A: stats + epilogue(t) + push fnA
        stats32(sm + MLA_F, cg, tid, sm + MRA_F);
        __syncthreads();
        float fnA[4];
        epilogue(a0, a1, sm + MRA_F, xrA, sm + FBA_F(pbuf),
                 (unsigned)(FBA_F(pbuf) * 4), lane, ob, cbase, hasL, hasR,
                 pbP, pbL0, pbL1, pbR0, pbR1, fnA);
        carr();                                    // p2: releases fnA + mailB

        // hide p2: A writeback(t) from regs + prefetch xrA(t+1)
        {
            float* dstA = fwd ? stkA : outA;
            writeback(fnA, dstA, row, cbase, ob, w0, lane);
            if (t == 255) writeback(fnA, outA, 255, cbase, ob, w0, lane);
            if (t < 510) {
                int nfwd = (t + 1) <= 255;
                int nrow = nfwd ? (t + 1) : 510 - (t + 1);
                prefetch_xr(nfwd ? xbA : stkA, nrow, cbase, ob, w0, lane, xrA);
            }
        }
        cwait();                                   // p2 done: mailB visible

        // ---- B: stats + epilogue(t) + push fnB
        stats32(sm + MLB_F, cg, tid, sm + MRB_F);
        __syncthreads();
        float fnB[4];
        epilogue(b0, b1, sm + MRB_F, xrB, sm + FBB_F(pbuf),
                 (unsigned)(FBB_F(pbuf) * 4), lane, ob, cbase, hasL, hasR,
                 pbP, pbL0, pbL1, pbR0, pbR1, fnB);
        carr();                                    // p3: releases fnB

        // hide p3: B writeback(t) + prefetch xrB(t+1)
        {
            float* dstB = fwd ? stkB : outB;
            writeback(fnB, dstB, row, cbase, ob, w0, lane);
            if (t == 255) writeback(fnB, outB, 255, cbase, ob, w0, lane);
            if (t < 510) {
                int nfwd = (t + 1) <= 255;
                int nrow = nfwd ? (t + 1) : 510 - (t + 1);
                prefetch_xr(nfwd ? xbB : stkB, nrow, cbase, ob, w0, lane, xrB);
            }
        }
        cwait();                                   // p3 done: fnA+fnB delivered
    }

    // no CTA exits while peers may still address its smem
    csync();
}

extern "C" void kernel_launch(void* const* d_in, const int* in_sizes, int n_in,
                              void* d_out, int out_size)
{
    (void)in_sizes; (void)n_in; (void)out_size;
    const float* x  = (const float*)d_in[0];
    const float* Wg = (const float*)d_in[1];
    // d_in[2] (bias) cancels through InstanceNorm — skipped.
    float* out = (float*)d_out;

    cudaStreamCaptureStatus cs = cudaStreamCaptureStatusNone;
    cudaStreamIsCapturing(0, &cs);
    if (cs == cudaStreamCaptureStatusNone) {
        cudaFuncSetAttribute(dirconv_kernel,
                             cudaFuncAttributeNonPortableClusterSizeAllowed, 1);
        cudaFuncSetAttribute(dirconv_kernel,
                             cudaFuncAttributeMaxDynamicSharedMemorySize, SMEM_BYTES);
    }

    dirconv_kernel<<<(Nn / 2) * Pp, NT, SMEM_BYTES>>>(x, Wg, out);
}